// round 2
// baseline (speedup 1.0000x reference)
#include <cuda_runtime.h>

// Problem constants
#define NB   32
#define CIN  256
#define COUTC 256
#define TT   128
#define VV   25
#define KK   3
#define VP   26              // v padded to even for f32x2 packing
#define OTOT (KK*COUTC)      // 768
#define NBLK (NB*TT)         // 4096 (n,t) blocks
#define CNT  (NB*TT*VV)      // 102400 elements per channel for BN stats
#define BN_EPS 1e-5f

typedef unsigned long long ull;

// ---------------- scratch (device globals; no allocs allowed) ----------------
__device__ __align__(16) float g_Wt[CIN * OTOT];          // W transposed: [ci][o]
__device__ __align__(16) float g_z[NB * COUTC * TT * VV]; // pre-BN activations (~105 MB)
__device__ float g_psum[COUTC * NBLK];                    // per-(c,block) partial sums
__device__ float g_psq [COUTC * NBLK];                    // per-(c,block) partial sumsq
__device__ float g_ss  [2 * COUTC];                       // [scale | shift]

// ---------------- f32x2 packed helpers ----------------
__device__ __forceinline__ ull pack2(float lo, float hi) {
    ull r; asm("mov.b64 %0, {%1,%2};" : "=l"(r) : "f"(lo), "f"(hi)); return r;
}
__device__ __forceinline__ void unpack2(ull a, float &lo, float &hi) {
    asm("mov.b64 {%0,%1}, %2;" : "=f"(lo), "=f"(hi) : "l"(a));
}
__device__ __forceinline__ ull fma2(ull a, ull b, ull c) {
    ull d; asm("fma.rn.f32x2 %0, %1, %2, %3;" : "=l"(d) : "l"(a), "l"(b), "l"(c)); return d;
}

// ---------------- kernel 0: transpose W [768,256] -> Wt [256,768] ----------------
__global__ void k_transpose(const float* __restrict__ W) {
    __shared__ float tile[32][33];
    int c0 = blockIdx.x * 32;   // ci tile base (0..255)
    int o0 = blockIdx.y * 32;   // o tile base  (0..767)
    int tx = threadIdx.x, ty = threadIdx.y;
    tile[ty][tx] = W[(o0 + ty) * CIN + (c0 + tx)];   // coalesced read along ci
    __syncthreads();
    g_Wt[(c0 + ty) * OTOT + (o0 + tx)] = tile[tx][ty]; // coalesced write along o
}

// ---------------- kernel 1: fused conv1x1 + adjacency + BN partial stats ----------------
// One block per (n,t). Thread c owns output channel c. f32x2-packed along v.
__global__ __launch_bounds__(256) void k_main(const float* __restrict__ x,
                                              const float* __restrict__ A,
                                              const float* __restrict__ b) {
    __shared__ __align__(16) float Xs[CIN][VP];        // 26.6 KB, pad col = 0
    __shared__ __align__(16) float As[KK][VV][VP];     // 7.8 KB,  pad col = 0

    const int bx = blockIdx.x;
    const int n = bx >> 7;        // bx / TT
    const int t = bx & (TT - 1);  // bx % TT
    const int c = threadIdx.x;

    // stage A (k,v,w) padded
    for (int i = c; i < KK * VV * VP; i += 256) {
        int k = i / (VV * VP);
        int r = i - k * (VV * VP);
        int v = r / VP;
        int w = r - v * VP;
        As[k][v][w] = (w < VV) ? A[(k * VV + v) * VV + w] : 0.f;
    }
    // stage X row for channel c
    {
        const float* xp = x + ((size_t)(n * CIN + c) * TT + t) * VV;
        #pragma unroll
        for (int v = 0; v < VV; v++) Xs[c][v] = xp[v];
        Xs[c][VV] = 0.f;
    }
    __syncthreads();

    ull zacc[13];
    #pragma unroll
    for (int j = 0; j < 13; j++) zacc[j] = 0ull;

    #pragma unroll
    for (int k = 0; k < KK; k++) {
        const int o = k * COUTC + c;
        const float bo = b[o];
        const ull b2 = pack2(bo, bo);
        ull acc[13];
        #pragma unroll
        for (int j = 0; j < 13; j++) acc[j] = b2;

        const float* wp = g_Wt + o;                  // column o, stride OTOT (coalesced across c)
        #pragma unroll 4
        for (int ci = 0; ci < CIN; ci++) {
            const float wv = wp[(size_t)ci * OTOT];
            const ull w2 = pack2(wv, wv);
            const ull* xr = (const ull*)Xs[ci];      // broadcast LDS.64
            #pragma unroll
            for (int j = 0; j < 13; j++) acc[j] = fma2(w2, xr[j], acc[j]);
        }
        // fold adjacency A_k: zacc[w] += Y_k[v] * A[k][v][w]
        #pragma unroll
        for (int v = 0; v < VV; v++) {
            float lo, hi; unpack2(acc[v >> 1], lo, hi);
            const float yv = (v & 1) ? hi : lo;
            const ull y2 = pack2(yv, yv);
            const ull* ar = (const ull*)As[k][v];
            #pragma unroll
            for (int j = 0; j < 13; j++) zacc[j] = fma2(y2, ar[j], zacc[j]);
        }
    }

    // unpack, write z, accumulate per-channel block partials
    float s1 = 0.f, s2 = 0.f;
    float* zp = g_z + ((size_t)(n * COUTC + c) * TT + t) * VV;
    #pragma unroll
    for (int j = 0; j < 13; j++) {
        float lo, hi; unpack2(zacc[j], lo, hi);
        const int w = 2 * j;
        zp[w] = lo; s1 += lo; s2 += lo * lo;
        if (w + 1 < VV) { zp[w + 1] = hi; s1 += hi; s2 += hi * hi; }
    }
    g_psum[c * NBLK + bx] = s1;
    g_psq [c * NBLK + bx] = s2;
}

// ---------------- kernel 2: finalize BN stats per channel ----------------
__global__ void k_stats(const float* __restrict__ gamma, const float* __restrict__ beta) {
    const int c = blockIdx.x;
    const int tid = threadIdx.x;
    float s1 = 0.f, s2 = 0.f;
    const float* ps = g_psum + c * NBLK;
    const float* pq = g_psq  + c * NBLK;
    for (int i = tid; i < NBLK; i += 256) { s1 += ps[i]; s2 += pq[i]; }
    __shared__ float r1[256], r2[256];
    r1[tid] = s1; r2[tid] = s2;
    __syncthreads();
    for (int s = 128; s > 0; s >>= 1) {
        if (tid < s) { r1[tid] += r1[tid + s]; r2[tid] += r2[tid + s]; }
        __syncthreads();
    }
    if (tid == 0) {
        const float inv = 1.0f / (float)CNT;
        const float mean = r1[0] * inv;
        const float var  = r2[0] * inv - mean * mean;
        const float sc   = gamma[c] * rsqrtf(var + BN_EPS);
        g_ss[c]          = sc;
        g_ss[COUTC + c]  = beta[c] - mean * sc;
    }
}

// ---------------- kernel 3: normalize + ReLU (float4) ----------------
// 26,214,400 floats = 6,553,600 float4. Each (n,c) row = 3200 floats = 800 float4.
__global__ void k_norm(float* __restrict__ out) {
    const int i4 = blockIdx.x * blockDim.x + threadIdx.x;
    const int c = (i4 / 800) & (COUTC - 1);
    const float sc = g_ss[c];
    const float sh = g_ss[COUTC + c];
    const float4 z = ((const float4*)g_z)[i4];
    float4 o;
    o.x = fmaxf(0.f, fmaf(z.x, sc, sh));
    o.y = fmaxf(0.f, fmaf(z.y, sc, sh));
    o.z = fmaxf(0.f, fmaf(z.z, sc, sh));
    o.w = fmaxf(0.f, fmaf(z.w, sc, sh));
    ((float4*)out)[i4] = o;
}

// ---------------- launch ----------------
extern "C" void kernel_launch(void* const* d_in, const int* in_sizes, int n_in,
                              void* d_out, int out_size) {
    const float* x     = (const float*)d_in[0];  // [32,256,128,25]
    const float* A     = (const float*)d_in[1];  // [3,25,25]
    const float* W     = (const float*)d_in[2];  // [768,256]
    const float* b     = (const float*)d_in[3];  // [768]
    const float* gamma = (const float*)d_in[4];  // [256]
    const float* beta  = (const float*)d_in[5];  // [256]
    float* out = (float*)d_out;

    k_transpose<<<dim3(CIN / 32, OTOT / 32), dim3(32, 32)>>>(W);
    k_main<<<NBLK, 256>>>(x, A, b);
    k_stats<<<COUTC, 256>>>(gamma, beta);
    k_norm<<<(NB * COUTC * TT * VV / 4) / 256, 256>>>(out);
}

// round 5
// speedup vs baseline: 3.2267x; 3.2267x over previous
#include <cuda_runtime.h>
#include <cstdint>

// ---------------- problem constants ----------------
#define NB    32
#define CIN   256
#define COUTC 256
#define TT    128
#define VV    25
#define KK    3
#define QQ    (TT*VV)       // 3200 pixels per n
#define QTOT  (NB*QQ)       // 102400
#define MTOT  768           // reduction dim m = (k,ci)
#define BN_EPS 1e-5f
#define CNT   (NB*TT*VV)    // 102400 per-channel count

// ---------------- GEMM tiling ----------------
#define BM    128           // c tile
#define BNQ   128           // q tile
#define BK    32
#define NKC   24            // 768/32
#define NQT2  800           // 102400/128
#define NPART 3200          // partials per channel = NQT2 * 4 (one per n-warp-col)

// padded smem rows: 32 floats + 4 pad
#define ROWF    36
#define TILE_F  (BM*ROWF)           // 4608 floats per tile
#define SMEM_GEMM (4*TILE_F*4)      // 73728 bytes (A0,A1,X0,X1)

typedef unsigned long long ull;

// ---------------- device scratch ----------------
__device__ __align__(16) float g_W2[COUTC * MTOT];             // tf32-rounded W [c][m]
__device__ __align__(16) float g_XA[(size_t)QTOT * MTOT];      // tf32-rounded folded input [q_global][m]
__device__ __align__(16) float g_z [(size_t)NB * COUTC * QQ];  // pre-BN activations
__device__ float g_zb  [COUTC * VV];                           // bias fold [c][w]
__device__ float g_psum[COUTC * NPART];
__device__ float g_psq [COUTC * NPART];
__device__ float g_ss  [2 * COUTC];

// ---------------- helpers ----------------
__device__ __forceinline__ uint32_t smem_u32(const void* p) {
    uint32_t a;
    asm("{ .reg .u64 t; cvta.to.shared.u64 t, %1; cvt.u32.u64 %0, t; }" : "=r"(a) : "l"(p));
    return a;
}
__device__ __forceinline__ ull pack2(float lo, float hi) {
    ull r; asm("mov.b64 %0, {%1,%2};" : "=l"(r) : "f"(lo), "f"(hi)); return r;
}
__device__ __forceinline__ void unpack2(ull a, float &lo, float &hi) {
    asm("mov.b64 {%0,%1}, %2;" : "=f"(lo), "=f"(hi) : "l"(a));
}
__device__ __forceinline__ ull fma2(ull a, ull b, ull c) {
    ull d; asm("fma.rn.f32x2 %0, %1, %2, %3;" : "=l"(d) : "l"(a), "l"(b), "l"(c)); return d;
}
__device__ __forceinline__ float totf32(float f) {
    uint32_t u; asm("cvt.rna.tf32.f32 %0, %1;" : "=r"(u) : "f"(f));
    return __uint_as_float(u);
}

#define CP_ASYNC16(dst, src) \
    asm volatile("cp.async.cg.shared.global [%0], [%1], 16;" :: "r"(dst), "l"(src))
#define CP_COMMIT() asm volatile("cp.async.commit_group;" ::: "memory")
#define CP_WAIT1()  asm volatile("cp.async.wait_group 1;"  ::: "memory")

__device__ __forceinline__ void mma_tf32(float* c, const uint32_t* a, const uint32_t* b) {
    asm volatile(
        "mma.sync.aligned.m16n8k8.row.col.f32.tf32.tf32.f32 "
        "{%0,%1,%2,%3}, {%4,%5,%6,%7}, {%8,%9}, {%0,%1,%2,%3};"
        : "+f"(c[0]), "+f"(c[1]), "+f"(c[2]), "+f"(c[3])
        : "r"(a[0]), "r"(a[1]), "r"(a[2]), "r"(a[3]), "r"(b[0]), "r"(b[1]));
}

// ---------------- kernel: W re-layout + tf32 round ----------------
// W[o=k*256+c][ci] -> W2[c][k*256+ci]
__global__ void k_w2(const float* __restrict__ W) {
    const int o = blockIdx.x;
    const int ci = threadIdx.x;
    const int c = o & 255, k = o >> 8;
    g_W2[c * MTOT + k * 256 + ci] = totf32(W[o * 256 + ci]);
}

// ---------------- kernel: bias fold term ----------------
__global__ void k_zb(const float* __restrict__ A, const float* __restrict__ b) {
    const int w = blockIdx.x;
    const int c = threadIdx.x;
    float s = 0.f;
    for (int k = 0; k < KK; k++) {
        float sa = 0.f;
        for (int v = 0; v < VV; v++) sa += A[(k * VV + v) * VV + w];
        s += b[k * 256 + c] * sa;
    }
    g_zb[c * VV + w] = s;
}

// ---------------- kernel: fold adjacency into input ----------------
// XA[(n*3200 + t*25 + w)][k*256+ci] = tf32( sum_v X[n][ci][t][v] * A[k][v][w] )
__global__ __launch_bounds__(128) void k_prep(const float* __restrict__ x,
                                              const float* __restrict__ A) {
    __shared__ ull As2[KK][VV][13];
    const int bx = blockIdx.x;
    const int n = bx >> 7;
    const int t = bx & (TT - 1);
    const int tid = threadIdx.x;

    for (int i = tid; i < KK * VV * 13; i += 128) {
        int k = i / (VV * 13);
        int r = i - k * (VV * 13);
        int v = r / 13, j = r - v * 13;
        float lo = A[(k * VV + v) * VV + 2 * j];
        float hi = (2 * j + 1 < VV) ? A[(k * VV + v) * VV + 2 * j + 1] : 0.f;
        As2[k][v][j] = pack2(lo, hi);
    }

    float xa[VV], xb[VV];
    {
        const float* pa = x + ((size_t)(n * CIN + tid) * TT + t) * VV;
        const float* pb = x + ((size_t)(n * CIN + tid + 128) * TT + t) * VV;
        #pragma unroll
        for (int v = 0; v < VV; v++) { xa[v] = pa[v]; xb[v] = pb[v]; }
    }
    __syncthreads();

    for (int k = 0; k < KK; k++) {
        ull za[13], zq[13];
        #pragma unroll
        for (int j = 0; j < 13; j++) { za[j] = 0ull; zq[j] = 0ull; }
        for (int v = 0; v < VV; v++) {
            const ull a2 = pack2(xa[v], xa[v]);
            const ull b2 = pack2(xb[v], xb[v]);
            #pragma unroll
            for (int j = 0; j < 13; j++) {
                const ull m = As2[k][v][j];
                za[j] = fma2(a2, m, za[j]);
                zq[j] = fma2(b2, m, zq[j]);
            }
        }
        const size_t rowbase = ((size_t)n * QQ + t * VV) * MTOT + k * 256;
        #pragma unroll
        for (int j = 0; j < 13; j++) {
            float lo, hi;
            unpack2(za[j], lo, hi);
            g_XA[rowbase + (size_t)(2 * j) * MTOT + tid] = totf32(lo);
            if (2 * j + 1 < VV) g_XA[rowbase + (size_t)(2 * j + 1) * MTOT + tid] = totf32(hi);
            unpack2(zq[j], lo, hi);
            g_XA[rowbase + (size_t)(2 * j) * MTOT + 128 + tid] = totf32(lo);
            if (2 * j + 1 < VV) g_XA[rowbase + (size_t)(2 * j + 1) * MTOT + 128 + tid] = totf32(hi);
        }
    }
}

// ---------------- kernel: warp-MMA tf32 GEMM + fused epilogue ----------------
// z[c][q] = sum_m W2[c][m] * XA[q][m] + zb[c][q%25];  BN partials out.
__global__ __launch_bounds__(256) void k_gemm() {
    extern __shared__ float sm[];
    // layout: A stage0 | A stage1 | X stage0 | X stage1, each TILE_F floats
    float* Asm = sm;
    float* Xsm = sm + 2 * TILE_F;

    const int tid  = threadIdx.x;
    const int wid  = tid >> 5;
    const int lane = tid & 31;
    const int gid  = lane >> 2;      // groupID (row within frag)
    const int tg   = lane & 3;       // thread-in-group (k / col pair)
    const int wm   = wid >> 2;       // warp row (0..1) -> 64 c-rows
    const int wn   = wid & 3;        // warp col (0..3) -> 32 q-cols

    const int c0 = blockIdx.x * BM;
    const int q0 = blockIdx.y * BNQ;             // global q
    const int n    = q0 / QQ;
    const int qloc = q0 - n * QQ;

    // cp.async staging: per thread 4 A lines + 4 X lines (16B each)
    const int lrow = tid >> 3;        // 0..31 (+32 per u)
    const int lc4  = tid & 7;         // 16B column
    const uint32_t sbase = smem_u32(sm);

    auto load_tiles = [&](int kc, int s) {
        const float* ga = g_W2 + (size_t)(c0 + lrow) * MTOT + kc * BK + lc4 * 4;
        const float* gx = g_XA + (size_t)(q0 + lrow) * MTOT + kc * BK + lc4 * 4;
        uint32_t da = sbase + (uint32_t)(s * TILE_F + lrow * ROWF + lc4 * 4) * 4;
        uint32_t dx = sbase + (uint32_t)((2 + s) * TILE_F + lrow * ROWF + lc4 * 4) * 4;
        #pragma unroll
        for (int u = 0; u < 4; u++) {
            CP_ASYNC16(da + u * 32 * ROWF * 4, ga + (size_t)u * 32 * MTOT);
            CP_ASYNC16(dx + u * 32 * ROWF * 4, gx + (size_t)u * 32 * MTOT);
        }
    };

    float acc[4][4][4];
    #pragma unroll
    for (int mf = 0; mf < 4; mf++)
        #pragma unroll
        for (int nf = 0; nf < 4; nf++)
            #pragma unroll
            for (int j = 0; j < 4; j++) acc[mf][nf][j] = 0.f;

    load_tiles(0, 0);
    CP_COMMIT();

    for (int kc = 0; kc < NKC; kc++) {
        const int s = kc & 1;
        if (kc + 1 < NKC) load_tiles(kc + 1, s ^ 1);
        CP_COMMIT();
        CP_WAIT1();
        __syncthreads();

        const float* Ab = Asm + s * TILE_F + (wm * 64 + gid) * ROWF;
        const float* Xb = Xsm + s * TILE_F + (wn * 32 + gid) * ROWF;
        #pragma unroll
        for (int k8 = 0; k8 < 4; k8++) {
            const int kk = k8 * 8 + tg;
            uint32_t afr[4][4];
            #pragma unroll
            for (int mf = 0; mf < 4; mf++) {
                const float* p = Ab + mf * 16 * ROWF;
                afr[mf][0] = __float_as_uint(p[kk]);
                afr[mf][1] = __float_as_uint(p[8 * ROWF + kk]);
                afr[mf][2] = __float_as_uint(p[kk + 4]);
                afr[mf][3] = __float_as_uint(p[8 * ROWF + kk + 4]);
            }
            uint32_t bfr[4][2];
            #pragma unroll
            for (int nf = 0; nf < 4; nf++) {
                const float* p = Xb + nf * 8 * ROWF;
                bfr[nf][0] = __float_as_uint(p[kk]);
                bfr[nf][1] = __float_as_uint(p[kk + 4]);
            }
            #pragma unroll
            for (int mf = 0; mf < 4; mf++)
                #pragma unroll
                for (int nf = 0; nf < 4; nf++)
                    mma_tf32(acc[mf][nf], afr[mf], bfr[nf]);
        }
        __syncthreads();
    }

    // ---- epilogue: +zb, z write, BN partials ----
    float s1[4][2], s2[4][2];
    #pragma unroll
    for (int mf = 0; mf < 4; mf++) { s1[mf][0] = s1[mf][1] = 0.f; s2[mf][0] = s2[mf][1] = 0.f; }

    #pragma unroll
    for (int mf = 0; mf < 4; mf++) {
        const int r0 = c0 + wm * 64 + mf * 16 + gid;   // and r0+8
        #pragma unroll
        for (int nf = 0; nf < 4; nf++) {
            const int col = qloc + wn * 32 + nf * 8 + tg * 2;
            const int w0 = col % VV;
            const int w1 = (w0 + 1 == VV) ? 0 : w0 + 1;
            const float zb00 = g_zb[r0 * VV + w0],       zb01 = g_zb[r0 * VV + w1];
            const float zb10 = g_zb[(r0 + 8) * VV + w0], zb11 = g_zb[(r0 + 8) * VV + w1];
            float v00 = acc[mf][nf][0] + zb00;
            float v01 = acc[mf][nf][1] + zb01;
            float v10 = acc[mf][nf][2] + zb10;
            float v11 = acc[mf][nf][3] + zb11;
            s1[mf][0] += v00 + v01;  s2[mf][0] += v00 * v00 + v01 * v01;
            s1[mf][1] += v10 + v11;  s2[mf][1] += v10 * v10 + v11 * v11;
            float* zp0 = g_z + (size_t)(n * COUTC + r0) * QQ + col;
            float* zp1 = g_z + (size_t)(n * COUTC + r0 + 8) * QQ + col;
            *(float2*)zp0 = make_float2(v00, v01);
            *(float2*)zp1 = make_float2(v10, v11);
        }
    }
    // reduce over the 4-lane quad (same rows, different cols)
    #pragma unroll
    for (int mf = 0; mf < 4; mf++)
        #pragma unroll
        for (int h = 0; h < 2; h++) {
            s1[mf][h] += __shfl_xor_sync(0xffffffffu, s1[mf][h], 1);
            s1[mf][h] += __shfl_xor_sync(0xffffffffu, s1[mf][h], 2);
            s2[mf][h] += __shfl_xor_sync(0xffffffffu, s2[mf][h], 1);
            s2[mf][h] += __shfl_xor_sync(0xffffffffu, s2[mf][h], 2);
        }
    if (tg == 0) {
        const int slot = blockIdx.y * 4 + wn;
        #pragma unroll
        for (int mf = 0; mf < 4; mf++)
            #pragma unroll
            for (int h = 0; h < 2; h++) {
                const int r = c0 + wm * 64 + mf * 16 + gid + h * 8;
                g_psum[r * NPART + slot] = s1[mf][h];
                g_psq [r * NPART + slot] = s2[mf][h];
            }
    }
}

// ---------------- kernel: finalize BN stats ----------------
__global__ void k_stats(const float* __restrict__ gamma, const float* __restrict__ beta) {
    const int c = blockIdx.x;
    const int tid = threadIdx.x;
    float s1 = 0.f, s2 = 0.f;
    const float* ps = g_psum + c * NPART;
    const float* pq = g_psq  + c * NPART;
    for (int i = tid; i < NPART; i += 256) { s1 += ps[i]; s2 += pq[i]; }
    __shared__ float r1[256], r2[256];
    r1[tid] = s1; r2[tid] = s2;
    __syncthreads();
    for (int s = 128; s > 0; s >>= 1) {
        if (tid < s) { r1[tid] += r1[tid + s]; r2[tid] += r2[tid + s]; }
        __syncthreads();
    }
    if (tid == 0) {
        const float inv  = 1.0f / (float)CNT;
        const float mean = r1[0] * inv;
        const float var  = r2[0] * inv - mean * mean;
        const float sc   = gamma[c] * rsqrtf(var + BN_EPS);
        g_ss[c]         = sc;
        g_ss[COUTC + c] = beta[c] - mean * sc;
    }
}

// ---------------- kernel: normalize + ReLU ----------------
__global__ void k_norm(float* __restrict__ out) {
    const int i4 = blockIdx.x * blockDim.x + threadIdx.x;
    const int c = (i4 / 800) & (COUTC - 1);
    const float sc = g_ss[c];
    const float sh = g_ss[COUTC + c];
    const float4 z = ((const float4*)g_z)[i4];
    float4 o;
    o.x = fmaxf(0.f, fmaf(z.x, sc, sh));
    o.y = fmaxf(0.f, fmaf(z.y, sc, sh));
    o.z = fmaxf(0.f, fmaf(z.z, sc, sh));
    o.w = fmaxf(0.f, fmaf(z.w, sc, sh));
    ((float4*)out)[i4] = o;
}

// ---------------- launch ----------------
extern "C" void kernel_launch(void* const* d_in, const int* in_sizes, int n_in,
                              void* d_out, int out_size) {
    const float* x     = (const float*)d_in[0];
    const float* A     = (const float*)d_in[1];
    const float* W     = (const float*)d_in[2];
    const float* b     = (const float*)d_in[3];
    const float* gamma = (const float*)d_in[4];
    const float* beta  = (const float*)d_in[5];
    float* out = (float*)d_out;

    cudaFuncSetAttribute(k_gemm, cudaFuncAttributeMaxDynamicSharedMemorySize, SMEM_GEMM);

    k_w2  <<<MTOT, 256>>>(W);
    k_zb  <<<VV, 256>>>(A, b);
    k_prep<<<NB * TT, 128>>>(x, A);
    k_gemm<<<dim3(2, NQT2), 256, SMEM_GEMM>>>();
    k_stats<<<COUTC, 256>>>(gamma, beta);
    k_norm<<<(NB * COUTC * TT * VV / 4) / 256, 256>>>(out);
}